// round 13
// baseline (speedup 1.0000x reference)
#include <cuda_runtime.h>
#include <math.h>

#define B 4
#define H 8
#define T 8192
#define D 64
#define NC 128
#define W 64
#define NTOK (B*H*T)          /* 262144 */
#define NOUT (B*H*T*D)        /* 16777216 */
#define NBINS 4096
#define CANDCAP 512

typedef unsigned long long ull;

// packed fp32x2 FMA (Blackwell double-rate fp32; only reachable via PTX)
#define FMA2(acc, a, b) asm("fma.rn.f32x2 %0, %1, %2, %0;" : "+l"(acc) : "l"(a), "l"(b))
// vectorized float reduction to global (sm_90+)
#define RED4(p, a, b, c, d) asm volatile("red.global.add.v4.f32 [%0], {%1,%2,%3,%4};" :: "l"(p), "f"(a), "f"(b), "f"(c), "f"(d) : "memory")

__device__ __forceinline__ ull pk2(float a, float b) {
    ull r;
    asm("mov.b64 %0, {%1, %2};" : "=l"(r) : "r"(__float_as_uint(a)), "r"(__float_as_uint(b)));
    return r;
}
__device__ __forceinline__ float2 upk2(ull p) {
    unsigned lo, hi;
    asm("mov.b64 {%0, %1}, %2;" : "=r"(lo), "=r"(hi) : "l"(p));
    return make_float2(__uint_as_float(lo), __uint_as_float(hi));
}

// -------- device scratch (no allocations allowed) --------
__device__ float  g_dists[(size_t)B*H*2*NC*T];   // [bh][s][c][t]
__device__ float  g_mnorm2[H*NC];
__device__ int    g_qidx[B*H*NC*W];
__device__ int    g_kidx[B*H*NC*W];
__device__ float  g_cnt[NTOK];
__device__ double g_aux;

// ---------------------------------------------------------
__global__ void mnorm_kernel(const float* __restrict__ means) {
    int i = blockIdx.x * blockDim.x + threadIdx.x;
    if (i < H * NC) {
        const float* m = means + (size_t)i * D;
        float s = 0.f;
        #pragma unroll
        for (int d = 0; d < D; d++) { float x = m[d]; s += x * x; }
        g_mnorm2[i] = s;
    }
}

// ===================== dist: r3 cluster-pair layout + packed xD (no pk2 in loop) + out-zeroing =====================
// smem: mT [64][128] f32 (32KB, dead after loop -> epilogue overlays), xD [64][128] ull (64KB), s_xn2[128]
extern __shared__ float ds_dyn[];
__global__ __launch_bounds__(256, 2)
void dist_kernel(const float* __restrict__ q,
                 const float* __restrict__ k,
                 const float* __restrict__ means,
                 float* __restrict__ out) {
    float* mT    = ds_dyn;                        // [64][128] f32
    ull*   xD    = (ull*)(ds_dyn + 64 * 128);     // [64][128] packed (x,x)
    float* s_xn2 = (float*)(xD + 64 * 128);       // [128]
    // epilogue overlays (alias mT; touched only after post-loop barrier)
    float* amaxv = ds_dyn;                        // [128][16]
    int*   amaxi = (int*)(ds_dyn + 2048);         // [128][16]
    float* red   = ds_dyn + 4096;                 // [256]

    int h = blockIdx.y, b = blockIdx.z;
    int bh = b * H + h;
    int tile = blockIdx.x;
    int s = tile >> 6;
    int t0 = (tile & 63) * 128;
    int tid = threadIdx.x;

    // fold output zeroing into s=0 blocks (replaces the 67MB serial memset)
    if (s == 0) {
        float4* o4 = (float4*)out + ((((size_t)bh * T + t0) * D) >> 2);
        float4 z = make_float4(0.f, 0.f, 0.f, 0.f);
        #pragma unroll
        for (int i = 0; i < 8; i++) o4[tid + 256 * i] = z;
    }

    const float4* mh4 = (const float4*)(means + (size_t)h * NC * D);
    for (int i = tid; i < NC * 16; i += 256) {
        int c = i & 127, dq = i >> 7;
        float4 mv = mh4[c * 16 + dq];
        mT[(4*dq+0)*128 + c] = mv.x;
        mT[(4*dq+1)*128 + c] = mv.y;
        mT[(4*dq+2)*128 + c] = mv.z;
        mT[(4*dq+3)*128 + c] = mv.w;
    }

    if (tid < 128) {
        const float* src = s ? k : q;
        const float4* xr = (const float4*)(src + ((size_t)bh * T + t0 + tid) * D);
        float4 xv[16]; float n2 = 0.f;
        #pragma unroll
        for (int i = 0; i < 16; i++) {
            float4 v = xr[i]; xv[i] = v;
            n2 += v.x*v.x + v.y*v.y + v.z*v.z + v.w*v.w;
        }
        float nrm = sqrtf(n2);
        float inv = 1.0f / fmaxf(nrm, 1e-12f);
        s_xn2[tid] = n2 * inv * inv;
        #pragma unroll
        for (int i = 0; i < 16; i++) {
            float a0 = xv[i].x * inv, a1 = xv[i].y * inv;
            float a2 = xv[i].z * inv, a3 = xv[i].w * inv;
            xD[(4*i+0)*128 + tid] = pk2(a0, a0);
            xD[(4*i+1)*128 + tid] = pk2(a1, a1);
            xD[(4*i+2)*128 + tid] = pk2(a2, a2);
            xD[(4*i+3)*128 + tid] = pk2(a3, a3);
        }
    }
    __syncthreads();

    int tx = tid & 15, ty = tid >> 4;
    int cb = ty * 8;
    ull acc[8][4];
    #pragma unroll
    for (int j = 0; j < 8; j++)
        #pragma unroll
        for (int p = 0; p < 4; p++) acc[j][p] = 0ull;

    #pragma unroll 4
    for (int d = 0; d < 64; d++) {
        const float* mrow = mT + d * 128 + cb;
        ull m0 = *(const ull*)(mrow + 0);
        ull m1 = *(const ull*)(mrow + 2);
        ull m2 = *(const ull*)(mrow + 4);
        ull m3 = *(const ull*)(mrow + 6);
        const ull* xrow = xD + d * 128 + tx;
        #pragma unroll
        for (int j = 0; j < 8; j++) {
            ull xx = xrow[16 * j];
            FMA2(acc[j][0], xx, m0);
            FMA2(acc[j][1], xx, m1);
            FMA2(acc[j][2], xx, m2);
            FMA2(acc[j][3], xx, m3);
        }
    }
    __syncthreads();   // mT dead; epilogue overlays it

    size_t obase = (((size_t)bh * 2 + s) * NC) * T + t0;
    #pragma unroll
    for (int j = 0; j < 8; j++) {
        int tok = tx + 16 * j;
        float bv = -1e30f; int bc = 0;
        #pragma unroll
        for (int p = 0; p < 4; p++) {
            float2 vv = upk2(acc[j][p]);
            int c = cb + 2 * p;
            g_dists[obase + (size_t)c * T + tok]       = vv.x;
            g_dists[obase + (size_t)(c + 1) * T + tok] = vv.y;
            if (vv.x > bv) { bv = vv.x; bc = c; }
            if (vv.y > bv) { bv = vv.y; bc = c + 1; }
        }
        amaxv[tok * 16 + ty] = bv;
        amaxi[tok * 16 + ty] = bc;
    }
    __syncthreads();

    if (tid < 128) {
        float bv = -1e30f; int bc = 0;
        #pragma unroll
        for (int t2 = 0; t2 < 16; t2++) {
            float v = amaxv[tid * 16 + t2];
            if (v > bv) { bv = v; bc = amaxi[tid * 16 + t2]; }
        }
        red[tid] = s_xn2[tid] - 2.f * bv + g_mnorm2[h * NC + bc];
    } else red[tid] = 0.f;
    __syncthreads();
    for (int o = 128; o > 0; o >>= 1) {
        if (tid < o) red[tid] += red[tid + o];
        __syncthreads();
    }
    if (tid == 0) atomicAdd(&g_aux, (double)red[0]);
}

// ===================== topk: ROUND-10 exact (4 blocks/SM) =====================
__global__ __launch_bounds__(512, 4) void topk_kernel() {
    __shared__ int   hist[NBINS];
    __shared__ int   warpTot[16];
    __shared__ int   warpSuf[16];
    __shared__ int   s_bstar, s_nOut, s_nCand;
    __shared__ float candV[CANDCAP];
    __shared__ int   candI[CANDCAP];

    int bid = blockIdx.x;
    int c = bid % NC;
    int s = (bid / NC) & 1;
    int bh = bid / (2 * NC);
    int h = bh % H;
    int tid = threadIdx.x;
    int lane = tid & 31, wid = tid >> 5;

    const float* dpBase = g_dists + (((size_t)bh * 2 + s) * NC + c) * T;
    const float4* dp4 = (const float4*)dpBase;

    for (int i = tid; i < NBINS; i += 512) hist[i] = 0;
    if (tid == 0) { s_nOut = 0; s_nCand = 0; }

    float mn = sqrtf(g_mnorm2[h * NC + c]);
    float lo = -mn;
    float scaleb = (float)NBINS / (2.0f * mn);

    unsigned bpack[8];
    {
        float4 va = dp4[tid], vb = dp4[tid + 512];
        bpack[0] = (unsigned)min(max((int)((va.x - lo) * scaleb), 0), NBINS - 1)
                 | ((unsigned)min(max((int)((va.y - lo) * scaleb), 0), NBINS - 1) << 16);
        bpack[1] = (unsigned)min(max((int)((va.z - lo) * scaleb), 0), NBINS - 1)
                 | ((unsigned)min(max((int)((va.w - lo) * scaleb), 0), NBINS - 1) << 16);
        bpack[2] = (unsigned)min(max((int)((vb.x - lo) * scaleb), 0), NBINS - 1)
                 | ((unsigned)min(max((int)((vb.y - lo) * scaleb), 0), NBINS - 1) << 16);
        bpack[3] = (unsigned)min(max((int)((vb.z - lo) * scaleb), 0), NBINS - 1)
                 | ((unsigned)min(max((int)((vb.w - lo) * scaleb), 0), NBINS - 1) << 16);
    }
    {
        float4 vc = dp4[tid + 1024], vd = dp4[tid + 1536];
        bpack[4] = (unsigned)min(max((int)((vc.x - lo) * scaleb), 0), NBINS - 1)
                 | ((unsigned)min(max((int)((vc.y - lo) * scaleb), 0), NBINS - 1) << 16);
        bpack[5] = (unsigned)min(max((int)((vc.z - lo) * scaleb), 0), NBINS - 1)
                 | ((unsigned)min(max((int)((vc.w - lo) * scaleb), 0), NBINS - 1) << 16);
        bpack[6] = (unsigned)min(max((int)((vd.x - lo) * scaleb), 0), NBINS - 1)
                 | ((unsigned)min(max((int)((vd.y - lo) * scaleb), 0), NBINS - 1) << 16);
        bpack[7] = (unsigned)min(max((int)((vd.z - lo) * scaleb), 0), NBINS - 1)
                 | ((unsigned)min(max((int)((vd.w - lo) * scaleb), 0), NBINS - 1) << 16);
    }
    __syncthreads();

    #pragma unroll
    for (int j = 0; j < 8; j++) {
        atomicAdd(&hist[bpack[j] & 0xffff], 1);
        atomicAdd(&hist[bpack[j] >> 16], 1);
    }
    __syncthreads();

    int orig = 0;
    #pragma unroll
    for (int bb = 0; bb < 8; bb++) orig += hist[tid * 8 + bb];
    int suf = orig;
    #pragma unroll
    for (int st = 1; st < 32; st <<= 1) {
        int o = __shfl_down_sync(0xffffffffu, suf, st);
        if (lane + st < 32) suf += o;
    }
    if (lane == 0) warpTot[wid] = suf;
    __syncthreads();
    if (wid == 0) {
        int t = (lane < 16) ? warpTot[lane] : 0;
        int v = t;
        #pragma unroll
        for (int st = 1; st < 16; st <<= 1) {
            int o = __shfl_down_sync(0xffffffffu, v, st);
            if (lane + st < 16) v += o;
        }
        if (lane < 16) warpSuf[lane] = v - t;
    }
    __syncthreads();

    int E = warpSuf[wid] + (suf - orig);
    if (E < W && E + orig >= W) {
        int cum = E;
        for (int bb = 7; bb >= 0; bb--) {
            int hc = hist[tid * 8 + bb];
            if (cum + hc >= W) { s_bstar = tid * 8 + bb; break; }
            cum += hc;
        }
    }
    __syncthreads();
    int bstar = s_bstar;

    int* outPtr = (s == 0 ? g_qidx : g_kidx) + ((size_t)bh * NC + c) * W;
    #pragma unroll
    for (int i = 0; i < 16; i++) {
        int bin = (int)((bpack[i >> 1] >> ((i & 1) * 16)) & 0xffffu);
        if (bin >= bstar) {
            int gi = 4 * (tid + 512 * (i >> 2)) + (i & 3);
            if (bin > bstar) {
                int p = atomicAdd(&s_nOut, 1);
                outPtr[p] = gi;
            } else {
                int p = atomicAdd(&s_nCand, 1);
                if (p < CANDCAP) { candI[p] = gi; candV[p] = dpBase[gi]; }
            }
        }
    }
    __syncthreads();

    if (tid == 0) {
        int nOut = s_nOut;
        int need = W - nOut;
        int ncand = min(s_nCand, CANDCAP);
        for (int r = 0; r < need; r++) {
            float bv = -1e30f; int bi = 0x7fffffff; int bp = -1;
            for (int m = 0; m < ncand; m++) {
                if (candI[m] >= 0) {
                    float vv = candV[m];
                    if (vv > bv || (vv == bv && candI[m] < bi)) { bv = vv; bi = candI[m]; bp = m; }
                }
            }
            outPtr[nOut + r] = bi;
            candI[bp] = -1;
        }
    }
}

// ===================== attn: 128 threads, 8q x 4k / 8q x 4d tiles (0.75x crossbar traffic) =====================
#define QT_S 68
#define SC_S 72
extern __shared__ float at_dyn[];
__global__ __launch_bounds__(128, 4)
void attn_kernel(const float* __restrict__ q,
                 const float* __restrict__ k,
                 const float* __restrict__ v,
                 const float* __restrict__ mem_key,
                 const float* __restrict__ mem_value,
                 float* __restrict__ out) {
    float* qT  = at_dyn;                 // [64 d][68] swizzled, cols = q rows (pre-scaled)
    float* kT  = at_dyn + 64 * QT_S;     // [64 d][68] swizzled, cols = k rows
    float* scS = at_dyn;                 // [65 j][72]  OVERLAY (qT/kT dead)
    float* vs  = at_dyn + 2 * 64 * QT_S; // [65 j][64 d]
    float* kMem = vs + 65 * 64;          // [64]
    int* qi = (int*)(kMem + 64);
    int* ki = qi + 64;

    int bid = blockIdx.x;
    int c = bid % NC;
    int bh = bid / NC;
    int h = bh % H;
    int tid = threadIdx.x;

    if (tid < 64)       qi[tid]      = g_qidx[((size_t)bh * NC + c) * W + tid];
    else if (tid < 128) ki[tid - 64] = g_kidx[((size_t)bh * NC + c) * W + tid - 64];
    __syncthreads();

    const float scale = 0.125f;   // d^-0.5 folded into q
    #pragma unroll
    for (int it = 0; it < 8; it++) {
        int idx = tid + 128 * it;           // 1024 slots = 64 rows x 16 float4
        int r = idx >> 4, c4 = idx & 15;
        int sw = 4 * (c4 & 7);
        float4 qv = ((const float4*)(q + ((size_t)bh * T + qi[r]) * D))[c4];
        qT[(4*c4+0)*QT_S + (r ^ sw)] = qv.x * scale;
        qT[(4*c4+1)*QT_S + (r ^ sw)] = qv.y * scale;
        qT[(4*c4+2)*QT_S + (r ^ sw)] = qv.z * scale;
        qT[(4*c4+3)*QT_S + (r ^ sw)] = qv.w * scale;
        float4 kv = ((const float4*)(k + ((size_t)bh * T + ki[r]) * D))[c4];
        kT[(4*c4+0)*QT_S + (r ^ sw)] = kv.x;
        kT[(4*c4+1)*QT_S + (r ^ sw)] = kv.y;
        kT[(4*c4+2)*QT_S + (r ^ sw)] = kv.z;
        kT[(4*c4+3)*QT_S + (r ^ sw)] = kv.w;
        ((float4*)(vs + r * 64))[c4] = ((const float4*)(v + ((size_t)bh * T + ki[r]) * D))[c4];
    }
    if (tid < 16) {
        ((float4*)kMem)[tid] = ((const float4*)(mem_key + ((size_t)h * NC + c) * D))[tid];
        ((float4*)(vs + 64 * 64))[tid] = ((const float4*)(mem_value + ((size_t)h * NC + c) * D))[tid];
    }
    __syncthreads();

    int tx = tid & 7, ty = tid >> 3;      // tx: 8 q-groups of 8; ty: 16 k-groups of 4
    int qb = 8 * tx, kb = 4 * ty;

    // ---- QK: 8q x 4k tile; acc[k][qpair] ----
    ull acc[4][4];
    #pragma unroll
    for (int i = 0; i < 4; i++)
        #pragma unroll
        for (int p = 0; p < 4; p++) acc[i][p] = 0ull;
    #pragma unroll
    for (int d = 0; d < 64; d++) {
        const int cw = 4 * ((d >> 2) & 7);
        const float* qrow = qT + d * QT_S;
        ulonglong2 qA = *(const ulonglong2*)(qrow + (qb ^ cw));          // q0..q3 (2 pairs)
        ulonglong2 qB = *(const ulonglong2*)(qrow + ((qb + 4) ^ cw));    // q4..q7
        float4 k4 = *(const float4*)(kT + d * QT_S + (kb ^ cw));
        ull k0 = pk2(k4.x, k4.x), k1 = pk2(k4.y, k4.y);
        ull k2 = pk2(k4.z, k4.z), k3 = pk2(k4.w, k4.w);
        FMA2(acc[0][0], qA.x, k0); FMA2(acc[0][1], qA.y, k0); FMA2(acc[0][2], qB.x, k0); FMA2(acc[0][3], qB.y, k0);
        FMA2(acc[1][0], qA.x, k1); FMA2(acc[1][1], qA.y, k1); FMA2(acc[1][2], qB.x, k1); FMA2(acc[1][3], qB.y, k1);
        FMA2(acc[2][0], qA.x, k2); FMA2(acc[2][1], qA.y, k2); FMA2(acc[2][2], qB.x, k2); FMA2(acc[2][3], qB.y, k2);
        FMA2(acc[3][0], qA.x, k3); FMA2(acc[3][1], qA.y, k3); FMA2(acc[3][2], qB.x, k3); FMA2(acc[3][3], qB.y, k3);
    }
    float memcol = 0.f;
    if (tid < 64) {
        #pragma unroll
        for (int d = 0; d < 64; d++)
            memcol += qT[d * QT_S + (tid ^ (4 * ((d >> 2) & 7)))] * kMem[d];
    }
    __syncthreads();   // qT/kT consumed; scS overlays

    #pragma unroll
    for (int i = 0; i < 4; i++) {
        ulonglong2 sA; sA.x = acc[i][0]; sA.y = acc[i][1];
        ulonglong2 sB; sB.x = acc[i][2]; sB.y = acc[i][3];
        *(ulonglong2*)(scS + (kb + i) * SC_S + qb)     = sA;
        *(ulonglong2*)(scS + (kb + i) * SC_S + qb + 4) = sB;
    }
    if (tid < 64) scS[64 * SC_S + tid] = memcol;
    __syncthreads();

    // ---- softmax: 2 threads per q row ----
    {
        int row = tid >> 1, part = tid & 1;
        float mx = -1e30f;
        for (int j = part; j < 65; j += 2) mx = fmaxf(mx, scS[j * SC_S + row]);
        mx = fmaxf(mx, __shfl_xor_sync(0xffffffffu, mx, 1));
        float sum = 0.f;
        for (int j = part; j < 65; j += 2) {
            float e = __expf(scS[j * SC_S + row] - mx);
            scS[j * SC_S + row] = e;
            sum += e;
        }
        sum += __shfl_xor_sync(0xffffffffu, sum, 1);
        float rinv = 1.0f / sum;
        for (int j = part; j < 65; j += 2) scS[j * SC_S + row] *= rinv;
    }
    __syncthreads();

    // ---- AV: 8q x 4d tile over 65 kv; o2[vcol][qpair] ----
    {
        int db = 4 * (tid >> 3);   // reuse ty
        ull o2[4][4];
        #pragma unroll
        for (int i = 0; i < 4; i++)
            #pragma unroll
            for (int p = 0; p < 4; p++) o2[i][p] = 0ull;
        #pragma unroll
        for (int j = 0; j < 65; j++) {
            const float* prow = scS + j * SC_S + qb;
            ulonglong2 pA = *(const ulonglong2*)(prow);
            ulonglong2 pB = *(const ulonglong2*)(prow + 4);
            float4 v4 = *(const float4*)(vs + j * 64 + db);
            ull v0 = pk2(v4.x, v4.x), v1 = pk2(v4.y, v4.y);
            ull v2 = pk2(v4.z, v4.z), v3 = pk2(v4.w, v4.w);
            FMA2(o2[0][0], pA.x, v0); FMA2(o2[0][1], pA.y, v0); FMA2(o2[0][2], pB.x, v0); FMA2(o2[0][3], pB.y, v0);
            FMA2(o2[1][0], pA.x, v1); FMA2(o2[1][1], pA.y, v1); FMA2(o2[1][2], pB.x, v1); FMA2(o2[1][3], pB.y, v1);
            FMA2(o2[2][0], pA.x, v2); FMA2(o2[2][1], pA.y, v2); FMA2(o2[2][2], pB.x, v2); FMA2(o2[2][3], pB.y, v2);
            FMA2(o2[3][0], pA.x, v3); FMA2(o2[3][1], pA.y, v3); FMA2(o2[3][2], pB.x, v3); FMA2(o2[3][3], pB.y, v3);
        }
        #pragma unroll
        for (int p = 0; p < 4; p++) {
            int r0 = qb + 2 * p;
            float* opA = out + ((size_t)bh * T + qi[r0])     * D + db;
            float* opB = out + ((size_t)bh * T + qi[r0 + 1]) * D + db;
            float2 f0 = upk2(o2[0][p]), f1 = upk2(o2[1][p]);
            float2 f2 = upk2(o2[2][p]), f3 = upk2(o2[3][p]);
            RED4(opA, f0.x, f1.x, f2.x, f3.x);
            RED4(opB, f0.y, f1.y, f2.y, f3.y);
        }
    }
    if (tid < 64) atomicAdd(&g_cnt[(size_t)bh * T + qi[tid]], 1.0f);
}

__global__ void finalize_kernel(float* out, int out_size) {
    int i = blockIdx.x * blockDim.x + threadIdx.x;
    if (i < NOUT / 4) {
        float4* o4 = (float4*)out;
        int r = i >> 4;
        float s = 1.0f / (g_cnt[r] + 1e-5f);
        float4 vv = o4[i];
        vv.x *= s; vv.y *= s; vv.z *= s; vv.w *= s;
        o4[i] = vv;
    }
    if (i == 0 && out_size > NOUT) {
        out[NOUT] = (float)(g_aux / ((double)B * H * 2 * T * D) * 1e-4);
    }
}

extern "C" void kernel_launch(void* const* d_in, const int* in_sizes, int n_in,
                              void* d_out, int out_size) {
    const float* q         = (const float*)d_in[0];
    const float* k         = (const float*)d_in[1];
    const float* v         = (const float*)d_in[2];
    const float* means     = (const float*)d_in[3];
    const float* mem_key   = (const float*)d_in[4];
    const float* mem_value = (const float*)d_in[5];
    float* out = (float*)d_out;

    int ds_smem = 64*128*4 + 64*128*8 + 128*4;            // 98816 (mT f32 + xD ull + xn2)
    int at_smem = (2*64*QT_S + 65*64 + 64 + 128) * 4;     // 52224
    cudaFuncSetAttribute(dist_kernel, cudaFuncAttributeMaxDynamicSharedMemorySize, ds_smem);
    cudaFuncSetAttribute(attn_kernel, cudaFuncAttributeMaxDynamicSharedMemorySize, at_smem);

    void* pcnt = nullptr; void* paux = nullptr;
    cudaGetSymbolAddress(&pcnt, g_cnt);
    cudaGetSymbolAddress(&paux, g_aux);

    // tail element (aux_loss) if out_size > NOUT must still be initialized; dist zeroes only NOUT
    if (out_size > NOUT)
        cudaMemsetAsync(out + NOUT, 0, (size_t)(out_size - NOUT) * sizeof(float), 0);
    cudaMemsetAsync(pcnt, 0, (size_t)NTOK * sizeof(float), 0);
    cudaMemsetAsync(paux, 0, sizeof(double), 0);
    mnorm_kernel<<<(H * NC + 255) / 256, 256>>>(means);
    dist_kernel<<<dim3(128, H, B), 256, ds_smem>>>(q, k, means, out);
    topk_kernel<<<B * H * 2 * NC, 512>>>();
    attn_kernel<<<B * H * NC, 128, at_smem>>>(q, k, v, mem_key, mem_value, out);
    finalize_kernel<<<(NOUT / 4 + 255) / 256, 256>>>(out, out_size);
}

// round 14
// speedup vs baseline: 1.1928x; 1.1928x over previous
#include <cuda_runtime.h>
#include <math.h>

#define B 4
#define H 8
#define T 8192
#define D 64
#define NC 128
#define W 64
#define NTOK (B*H*T)          /* 262144 */
#define NOUT (B*H*T*D)        /* 16777216 */
#define NBINS 4096
#define CANDCAP 512

typedef unsigned long long ull;

// packed fp32x2 FMA (Blackwell double-rate fp32; only reachable via PTX)
#define FMA2(acc, a, b) asm("fma.rn.f32x2 %0, %1, %2, %0;" : "+l"(acc) : "l"(a), "l"(b))
// vectorized float reduction to global (sm_90+)
#define RED4(p, a, b, c, d) asm volatile("red.global.add.v4.f32 [%0], {%1,%2,%3,%4};" :: "l"(p), "f"(a), "f"(b), "f"(c), "f"(d) : "memory")

__device__ __forceinline__ ull pk2(float a, float b) {
    ull r;
    asm("mov.b64 %0, {%1, %2};" : "=l"(r) : "r"(__float_as_uint(a)), "r"(__float_as_uint(b)));
    return r;
}
__device__ __forceinline__ float2 upk2(ull p) {
    unsigned lo, hi;
    asm("mov.b64 {%0, %1}, %2;" : "=r"(lo), "=r"(hi) : "l"(p));
    return make_float2(__uint_as_float(lo), __uint_as_float(hi));
}

// -------- device scratch (no allocations allowed) --------
__device__ float  g_dists[(size_t)B*H*2*NC*T];   // [bh][s][c][t]
__device__ float  g_mnorm2[H*NC];
__device__ int    g_qidx[B*H*NC*W];
__device__ int    g_kidx[B*H*NC*W];
__device__ float  g_cnt[NTOK];
__device__ double g_aux;

// ---------------------------------------------------------
__global__ void mnorm_kernel(const float* __restrict__ means) {
    int i = blockIdx.x * blockDim.x + threadIdx.x;
    if (i < H * NC) {
        const float* m = means + (size_t)i * D;
        float s = 0.f;
        #pragma unroll
        for (int d = 0; d < D; d++) { float x = m[d]; s += x * x; }
        g_mnorm2[i] = s;
    }
}

// ===================== dist: ROUND-3 exact + folded output zeroing =====================
extern __shared__ float ds_dyn[];
__global__ __launch_bounds__(256, 2)
void dist_kernel(const float* __restrict__ q,
                 const float* __restrict__ k,
                 const float* __restrict__ means,
                 float* __restrict__ out) {
    float* mT    = ds_dyn;                 // [64][128]
    float* xT    = mT + 64 * 128;          // [64][128]
    float* s_xn2 = xT + 64 * 128;          // [128]
    float* amaxv = s_xn2 + 128;            // [128][16]
    int*   amaxi = (int*)(amaxv + 128*16); // [128][16]
    float* red   = (float*)(amaxi + 128*16); // [256]

    int h = blockIdx.y, b = blockIdx.z;
    int bh = b * H + h;
    int tile = blockIdx.x;
    int s = tile >> 6;
    int t0 = (tile & 63) * 128;
    int tid = threadIdx.x;

    // fold output zeroing into s=0 blocks (replaces the 67MB serial memset;
    // dist is issue-bound, DRAM nearly idle, so these STG.128 are ~free)
    if (s == 0) {
        float4* o4 = (float4*)out + ((((size_t)bh * T + t0) * D) >> 2);
        float4 z = make_float4(0.f, 0.f, 0.f, 0.f);
        #pragma unroll
        for (int i = 0; i < 8; i++) o4[tid + 256 * i] = z;
    }

    const float4* mh4 = (const float4*)(means + (size_t)h * NC * D);
    for (int i = tid; i < NC * 16; i += 256) {
        int c = i & 127, dq = i >> 7;
        float4 mv = mh4[c * 16 + dq];
        mT[(4*dq+0)*128 + c] = mv.x;
        mT[(4*dq+1)*128 + c] = mv.y;
        mT[(4*dq+2)*128 + c] = mv.z;
        mT[(4*dq+3)*128 + c] = mv.w;
    }

    if (tid < 128) {
        const float* src = s ? k : q;
        const float4* xr = (const float4*)(src + ((size_t)bh * T + t0 + tid) * D);
        float4 xv[16]; float n2 = 0.f;
        #pragma unroll
        for (int i = 0; i < 16; i++) {
            float4 v = xr[i]; xv[i] = v;
            n2 += v.x*v.x + v.y*v.y + v.z*v.z + v.w*v.w;
        }
        float nrm = sqrtf(n2);
        float inv = 1.0f / fmaxf(nrm, 1e-12f);
        s_xn2[tid] = n2 * inv * inv;
        #pragma unroll
        for (int i = 0; i < 16; i++) {
            xT[(4*i+0)*128 + tid] = xv[i].x * inv;
            xT[(4*i+1)*128 + tid] = xv[i].y * inv;
            xT[(4*i+2)*128 + tid] = xv[i].z * inv;
            xT[(4*i+3)*128 + tid] = xv[i].w * inv;
        }
    }
    __syncthreads();

    int tx = tid & 15, ty = tid >> 4;
    int cb = ty * 8;
    ull acc[8][4];
    #pragma unroll
    for (int j = 0; j < 8; j++)
        #pragma unroll
        for (int p = 0; p < 4; p++) acc[j][p] = 0ull;

    #pragma unroll 4
    for (int d = 0; d < 64; d++) {
        const float* mrow = mT + d * 128 + cb;
        ull m0 = *(const ull*)(mrow + 0);
        ull m1 = *(const ull*)(mrow + 2);
        ull m2 = *(const ull*)(mrow + 4);
        ull m3 = *(const ull*)(mrow + 6);
        const float* xrow = xT + d * 128 + tx;
        #pragma unroll
        for (int j = 0; j < 8; j++) {
            float xv = xrow[16 * j];
            ull xx = pk2(xv, xv);
            FMA2(acc[j][0], xx, m0);
            FMA2(acc[j][1], xx, m1);
            FMA2(acc[j][2], xx, m2);
            FMA2(acc[j][3], xx, m3);
        }
    }

    size_t obase = (((size_t)bh * 2 + s) * NC) * T + t0;
    #pragma unroll
    for (int j = 0; j < 8; j++) {
        int tok = tx + 16 * j;
        float bv = -1e30f; int bc = 0;
        #pragma unroll
        for (int p = 0; p < 4; p++) {
            float2 vv = upk2(acc[j][p]);
            int c = cb + 2 * p;
            g_dists[obase + (size_t)c * T + tok]       = vv.x;
            g_dists[obase + (size_t)(c + 1) * T + tok] = vv.y;
            if (vv.x > bv) { bv = vv.x; bc = c; }
            if (vv.y > bv) { bv = vv.y; bc = c + 1; }
        }
        amaxv[tok * 16 + ty] = bv;
        amaxi[tok * 16 + ty] = bc;
    }
    __syncthreads();

    if (tid < 128) {
        float bv = -1e30f; int bc = 0;
        #pragma unroll
        for (int t2 = 0; t2 < 16; t2++) {
            float v = amaxv[tid * 16 + t2];
            if (v > bv) { bv = v; bc = amaxi[tid * 16 + t2]; }
        }
        red[tid] = s_xn2[tid] - 2.f * bv + g_mnorm2[h * NC + bc];
    } else red[tid] = 0.f;
    __syncthreads();
    for (int o = 128; o > 0; o >>= 1) {
        if (tid < o) red[tid] += red[tid + o];
        __syncthreads();
    }
    if (tid == 0) atomicAdd(&g_aux, (double)red[0]);
}

// ===================== topk: ROUND-10 exact (4 blocks/SM) + vectorized hist clear =====================
__global__ __launch_bounds__(512, 4) void topk_kernel() {
    __shared__ int   hist[NBINS];
    __shared__ int   warpTot[16];
    __shared__ int   warpSuf[16];
    __shared__ int   s_bstar, s_nOut, s_nCand;
    __shared__ float candV[CANDCAP];
    __shared__ int   candI[CANDCAP];

    int bid = blockIdx.x;
    int c = bid % NC;
    int s = (bid / NC) & 1;
    int bh = bid / (2 * NC);
    int h = bh % H;
    int tid = threadIdx.x;
    int lane = tid & 31, wid = tid >> 5;

    const float* dpBase = g_dists + (((size_t)bh * 2 + s) * NC + c) * T;
    const float4* dp4 = (const float4*)dpBase;

    {
        int4 z = make_int4(0, 0, 0, 0);
        ((int4*)hist)[tid]       = z;
        ((int4*)hist)[tid + 512] = z;
    }
    if (tid == 0) { s_nOut = 0; s_nCand = 0; }

    float mn = sqrtf(g_mnorm2[h * NC + c]);
    float lo = -mn;
    float scaleb = (float)NBINS / (2.0f * mn);

    unsigned bpack[8];
    {
        float4 va = dp4[tid], vb = dp4[tid + 512];
        bpack[0] = (unsigned)min(max((int)((va.x - lo) * scaleb), 0), NBINS - 1)
                 | ((unsigned)min(max((int)((va.y - lo) * scaleb), 0), NBINS - 1) << 16);
        bpack[1] = (unsigned)min(max((int)((va.z - lo) * scaleb), 0), NBINS - 1)
                 | ((unsigned)min(max((int)((va.w - lo) * scaleb), 0), NBINS - 1) << 16);
        bpack[2] = (unsigned)min(max((int)((vb.x - lo) * scaleb), 0), NBINS - 1)
                 | ((unsigned)min(max((int)((vb.y - lo) * scaleb), 0), NBINS - 1) << 16);
        bpack[3] = (unsigned)min(max((int)((vb.z - lo) * scaleb), 0), NBINS - 1)
                 | ((unsigned)min(max((int)((vb.w - lo) * scaleb), 0), NBINS - 1) << 16);
    }
    {
        float4 vc = dp4[tid + 1024], vd = dp4[tid + 1536];
        bpack[4] = (unsigned)min(max((int)((vc.x - lo) * scaleb), 0), NBINS - 1)
                 | ((unsigned)min(max((int)((vc.y - lo) * scaleb), 0), NBINS - 1) << 16);
        bpack[5] = (unsigned)min(max((int)((vc.z - lo) * scaleb), 0), NBINS - 1)
                 | ((unsigned)min(max((int)((vc.w - lo) * scaleb), 0), NBINS - 1) << 16);
        bpack[6] = (unsigned)min(max((int)((vd.x - lo) * scaleb), 0), NBINS - 1)
                 | ((unsigned)min(max((int)((vd.y - lo) * scaleb), 0), NBINS - 1) << 16);
        bpack[7] = (unsigned)min(max((int)((vd.z - lo) * scaleb), 0), NBINS - 1)
                 | ((unsigned)min(max((int)((vd.w - lo) * scaleb), 0), NBINS - 1) << 16);
    }
    __syncthreads();

    #pragma unroll
    for (int j = 0; j < 8; j++) {
        atomicAdd(&hist[bpack[j] & 0xffff], 1);
        atomicAdd(&hist[bpack[j] >> 16], 1);
    }
    __syncthreads();

    int orig = 0;
    #pragma unroll
    for (int bb = 0; bb < 8; bb++) orig += hist[tid * 8 + bb];
    int suf = orig;
    #pragma unroll
    for (int st = 1; st < 32; st <<= 1) {
        int o = __shfl_down_sync(0xffffffffu, suf, st);
        if (lane + st < 32) suf += o;
    }
    if (lane == 0) warpTot[wid] = suf;
    __syncthreads();
    if (wid == 0) {
        int t = (lane < 16) ? warpTot[lane] : 0;
        int v = t;
        #pragma unroll
        for (int st = 1; st < 16; st <<= 1) {
            int o = __shfl_down_sync(0xffffffffu, v, st);
            if (lane + st < 16) v += o;
        }
        if (lane < 16) warpSuf[lane] = v - t;
    }
    __syncthreads();

    int E = warpSuf[wid] + (suf - orig);
    if (E < W && E + orig >= W) {
        int cum = E;
        for (int bb = 7; bb >= 0; bb--) {
            int hc = hist[tid * 8 + bb];
            if (cum + hc >= W) { s_bstar = tid * 8 + bb; break; }
            cum += hc;
        }
    }
    __syncthreads();
    int bstar = s_bstar;

    int* outPtr = (s == 0 ? g_qidx : g_kidx) + ((size_t)bh * NC + c) * W;
    #pragma unroll
    for (int i = 0; i < 16; i++) {
        int bin = (int)((bpack[i >> 1] >> ((i & 1) * 16)) & 0xffffu);
        if (bin >= bstar) {
            int gi = 4 * (tid + 512 * (i >> 2)) + (i & 3);
            if (bin > bstar) {
                int p = atomicAdd(&s_nOut, 1);
                outPtr[p] = gi;
            } else {
                int p = atomicAdd(&s_nCand, 1);
                if (p < CANDCAP) { candI[p] = gi; candV[p] = dpBase[gi]; }
            }
        }
    }
    __syncthreads();

    if (tid == 0) {
        int nOut = s_nOut;
        int need = W - nOut;
        int ncand = min(s_nCand, CANDCAP);
        for (int r = 0; r < need; r++) {
            float bv = -1e30f; int bi = 0x7fffffff; int bp = -1;
            for (int m = 0; m < ncand; m++) {
                if (candI[m] >= 0) {
                    float vv = candV[m];
                    if (vv > bv || (vv == bv && candI[m] < bi)) { bv = vv; bi = candI[m]; bp = m; }
                }
            }
            outPtr[nOut + r] = bi;
            candI[bp] = -1;
        }
    }
}

// ===================== attn: ROUND-12 exact (256 thr, 4x4 tiles, swizzle, full unroll) =====================
#define QT_S 68
#define SC_S 72
extern __shared__ float at_dyn[];
__global__ __launch_bounds__(256, 4)
void attn_kernel(const float* __restrict__ q,
                 const float* __restrict__ k,
                 const float* __restrict__ v,
                 const float* __restrict__ mem_key,
                 const float* __restrict__ mem_value,
                 float* __restrict__ out) {
    float* qT  = at_dyn;                 // [64 d][68] swizzled, cols = q rows (pre-scaled)
    float* kT  = at_dyn + 64 * QT_S;     // [64 d][68] swizzled, cols = k rows
    float* scS = at_dyn;                 // [65 j][72]  OVERLAY (qT/kT dead)
    float* vs  = at_dyn + 2 * 64 * QT_S; // [65 j][64 d]
    float* kMem = vs + 65 * 64;          // [64]
    int* qi = (int*)(kMem + 64);
    int* ki = qi + 64;

    int bid = blockIdx.x;
    int c = bid % NC;
    int bh = bid / NC;
    int h = bh % H;
    int tid = threadIdx.x;

    if (tid < 64)       qi[tid]      = g_qidx[((size_t)bh * NC + c) * W + tid];
    else if (tid < 128) ki[tid - 64] = g_kidx[((size_t)bh * NC + c) * W + tid - 64];
    __syncthreads();

    const float scale = 0.125f;   // d^-0.5 folded into q
    #pragma unroll
    for (int it = 0; it < 4; it++) {
        int idx = tid + 256 * it;           // 1024 slots = 64 rows x 16 float4
        int r = idx >> 4, c4 = idx & 15;
        int sw = 4 * (c4 & 7);
        float4 qv = ((const float4*)(q + ((size_t)bh * T + qi[r]) * D))[c4];
        qT[(4*c4+0)*QT_S + (r ^ sw)] = qv.x * scale;
        qT[(4*c4+1)*QT_S + (r ^ sw)] = qv.y * scale;
        qT[(4*c4+2)*QT_S + (r ^ sw)] = qv.z * scale;
        qT[(4*c4+3)*QT_S + (r ^ sw)] = qv.w * scale;
        float4 kv = ((const float4*)(k + ((size_t)bh * T + ki[r]) * D))[c4];
        kT[(4*c4+0)*QT_S + (r ^ sw)] = kv.x;
        kT[(4*c4+1)*QT_S + (r ^ sw)] = kv.y;
        kT[(4*c4+2)*QT_S + (r ^ sw)] = kv.z;
        kT[(4*c4+3)*QT_S + (r ^ sw)] = kv.w;
        ((float4*)(vs + r * 64))[c4] = ((const float4*)(v + ((size_t)bh * T + ki[r]) * D))[c4];
    }
    if (tid < 16) {
        ((float4*)kMem)[tid] = ((const float4*)(mem_key + ((size_t)h * NC + c) * D))[tid];
        ((float4*)(vs + 64 * 64))[tid] = ((const float4*)(mem_value + ((size_t)h * NC + c) * D))[tid];
    }
    __syncthreads();

    int tx = tid & 15, ty = tid >> 4;
    int qb = 4 * tx, kb = 4 * ty;

    ull acc[2][4];
    #pragma unroll
    for (int p = 0; p < 2; p++)
        #pragma unroll
        for (int i = 0; i < 4; i++) acc[p][i] = 0ull;
    #pragma unroll
    for (int d = 0; d < 64; d++) {
        const int cw = 4 * ((d >> 2) & 7);
        ulonglong2 q2 = *(const ulonglong2*)(qT + d * QT_S + (qb ^ cw));
        float4 k4 = *(const float4*)(kT + d * QT_S + (kb ^ cw));
        ull k0 = pk2(k4.x, k4.x), k1 = pk2(k4.y, k4.y);
        ull k2 = pk2(k4.z, k4.z), k3 = pk2(k4.w, k4.w);
        FMA2(acc[0][0], q2.x, k0); FMA2(acc[1][0], q2.y, k0);
        FMA2(acc[0][1], q2.x, k1); FMA2(acc[1][1], q2.y, k1);
        FMA2(acc[0][2], q2.x, k2); FMA2(acc[1][2], q2.y, k2);
        FMA2(acc[0][3], q2.x, k3); FMA2(acc[1][3], q2.y, k3);
    }
    float memcol = 0.f;
    if (tid < 64) {
        #pragma unroll
        for (int d = 0; d < 64; d++)
            memcol += qT[d * QT_S + (tid ^ (4 * ((d >> 2) & 7)))] * kMem[d];
    }
    __syncthreads();   // qT/kT consumed; scS overlays

    #pragma unroll
    for (int i = 0; i < 4; i++) {
        ulonglong2 st; st.x = acc[0][i]; st.y = acc[1][i];
        *(ulonglong2*)(scS + (kb + i) * SC_S + qb) = st;
    }
    if (tid < 64) scS[64 * SC_S + tid] = memcol;
    __syncthreads();

    {
        int row = tid >> 2, part = tid & 3;
        float mx = -1e30f;
        for (int j = part; j < 65; j += 4) mx = fmaxf(mx, scS[j * SC_S + row]);
        mx = fmaxf(mx, __shfl_xor_sync(0xffffffffu, mx, 1));
        mx = fmaxf(mx, __shfl_xor_sync(0xffffffffu, mx, 2));
        float sum = 0.f;
        for (int j = part; j < 65; j += 4) {
            float e = __expf(scS[j * SC_S + row] - mx);
            scS[j * SC_S + row] = e;
            sum += e;
        }
        sum += __shfl_xor_sync(0xffffffffu, sum, 1);
        sum += __shfl_xor_sync(0xffffffffu, sum, 2);
        float rinv = 1.0f / sum;
        for (int j = part; j < 65; j += 4) scS[j * SC_S + row] *= rinv;
    }
    __syncthreads();

    {
        int db = 4 * ty;
        ull o2[2][4];
        #pragma unroll
        for (int p = 0; p < 2; p++)
            #pragma unroll
            for (int i = 0; i < 4; i++) o2[p][i] = 0ull;
        #pragma unroll
        for (int j = 0; j < 65; j++) {
            ulonglong2 p2 = *(const ulonglong2*)(scS + j * SC_S + qb);
            float4 v4 = *(const float4*)(vs + j * 64 + db);
            ull v0 = pk2(v4.x, v4.x), v1 = pk2(v4.y, v4.y);
            ull v2 = pk2(v4.z, v4.z), v3 = pk2(v4.w, v4.w);
            FMA2(o2[0][0], p2.x, v0); FMA2(o2[1][0], p2.y, v0);
            FMA2(o2[0][1], p2.x, v1); FMA2(o2[1][1], p2.y, v1);
            FMA2(o2[0][2], p2.x, v2); FMA2(o2[1][2], p2.y, v2);
            FMA2(o2[0][3], p2.x, v3); FMA2(o2[1][3], p2.y, v3);
        }
        #pragma unroll
        for (int p = 0; p < 2; p++) {
            int r0 = qb + 2 * p;
            float* opA = out + ((size_t)bh * T + qi[r0])     * D + db;
            float* opB = out + ((size_t)bh * T + qi[r0 + 1]) * D + db;
            float2 f0 = upk2(o2[p][0]), f1 = upk2(o2[p][1]);
            float2 f2 = upk2(o2[p][2]), f3 = upk2(o2[p][3]);
            RED4(opA, f0.x, f1.x, f2.x, f3.x);
            RED4(opB, f0.y, f1.y, f2.y, f3.y);
        }
    }
    if (tid < 64) atomicAdd(&g_cnt[(size_t)bh * T + qi[tid]], 1.0f);
}

__global__ void finalize_kernel(float* out, int out_size) {
    int i = blockIdx.x * blockDim.x + threadIdx.x;
    if (i < NOUT / 4) {
        float4* o4 = (float4*)out;
        int r = i >> 4;
        float s = 1.0f / (g_cnt[r] + 1e-5f);
        float4 vv = o4[i];
        vv.x *= s; vv.y *= s; vv.z *= s; vv.w *= s;
        o4[i] = vv;
    }
    if (i == 0 && out_size > NOUT) {
        out[NOUT] = (float)(g_aux / ((double)B * H * 2 * T * D) * 1e-4);
    }
}

extern "C" void kernel_launch(void* const* d_in, const int* in_sizes, int n_in,
                              void* d_out, int out_size) {
    const float* q         = (const float*)d_in[0];
    const float* k         = (const float*)d_in[1];
    const float* v         = (const float*)d_in[2];
    const float* means     = (const float*)d_in[3];
    const float* mem_key   = (const float*)d_in[4];
    const float* mem_value = (const float*)d_in[5];
    float* out = (float*)d_out;

    int ds_smem = (64*128 + 64*128 + 128 + 128*16 + 128*16 + 256) * 4;  // 83456
    int at_smem = (2*64*QT_S + 65*64 + 64 + 128) * 4;                   // 52224
    cudaFuncSetAttribute(dist_kernel, cudaFuncAttributeMaxDynamicSharedMemorySize, ds_smem);
    cudaFuncSetAttribute(attn_kernel, cudaFuncAttributeMaxDynamicSharedMemorySize, at_smem);

    void* pcnt = nullptr; void* paux = nullptr;
    cudaGetSymbolAddress(&pcnt, g_cnt);
    cudaGetSymbolAddress(&paux, g_aux);

    // out[0..NOUT) is zeroed inside dist_kernel (s==0 blocks); only the tail needs a memset
    if (out_size > NOUT)
        cudaMemsetAsync(out + NOUT, 0, (size_t)(out_size - NOUT) * sizeof(float), 0);
    cudaMemsetAsync(pcnt, 0, (size_t)NTOK * sizeof(float), 0);
    cudaMemsetAsync(paux, 0, sizeof(double), 0);
    mnorm_kernel<<<(H * NC + 255) / 256, 256>>>(means);
    dist_kernel<<<dim3(128, H, B), 256, ds_smem>>>(q, k, means, out);
    topk_kernel<<<B * H * 2 * NC, 512>>>();
    attn_kernel<<<B * H * NC, 256, at_smem>>>(q, k, v, mem_key, mem_value, out);
    finalize_kernel<<<(NOUT / 4 + 255) / 256, 256>>>(out, out_size);
}

// round 15
// speedup vs baseline: 1.2317x; 1.0327x over previous
#include <cuda_runtime.h>
#include <math.h>

#define B 4
#define H 8
#define T 8192
#define D 64
#define NC 128
#define W 64
#define NTOK (B*H*T)          /* 262144 */
#define NOUT (B*H*T*D)        /* 16777216 */
#define NBINS 4096
#define CANDCAP 512

typedef unsigned long long ull;

// packed fp32x2 FMA (Blackwell double-rate fp32; only reachable via PTX)
#define FMA2(acc, a, b) asm("fma.rn.f32x2 %0, %1, %2, %0;" : "+l"(acc) : "l"(a), "l"(b))
// vectorized float reduction to global (sm_90+)
#define RED4(p, a, b, c, d) asm volatile("red.global.add.v4.f32 [%0], {%1,%2,%3,%4};" :: "l"(p), "f"(a), "f"(b), "f"(c), "f"(d) : "memory")

__device__ __forceinline__ ull pk2(float a, float b) {
    ull r;
    asm("mov.b64 %0, {%1, %2};" : "=l"(r) : "r"(__float_as_uint(a)), "r"(__float_as_uint(b)));
    return r;
}
__device__ __forceinline__ float2 upk2(ull p) {
    unsigned lo, hi;
    asm("mov.b64 {%0, %1}, %2;" : "=r"(lo), "=r"(hi) : "l"(p));
    return make_float2(__uint_as_float(lo), __uint_as_float(hi));
}

// -------- device scratch (no allocations allowed) --------
__device__ float  g_dists[(size_t)B*H*2*NC*T];   // [bh][s][c][t]
__device__ float  g_mnorm2[H*NC];
__device__ int    g_qidx[B*H*NC*W];
__device__ int    g_kidx[B*H*NC*W];
__device__ float  g_cnt[NTOK];
__device__ double g_aux;

// ---------------------------------------------------------
__global__ void mnorm_kernel(const float* __restrict__ means) {
    int i = blockIdx.x * blockDim.x + threadIdx.x;
    if (i < H * NC) {
        const float* m = means + (size_t)i * D;
        float s = 0.f;
        #pragma unroll
        for (int d = 0; d < D; d++) { float x = m[d]; s += x * x; }
        g_mnorm2[i] = s;
    }
}

// ===================== dist: 4tok x 16cl tile (warp-uniform ty -> all m-loads broadcast) =====================
extern __shared__ float ds_dyn[];
__global__ __launch_bounds__(256, 2)
void dist_kernel(const float* __restrict__ q,
                 const float* __restrict__ k,
                 const float* __restrict__ means,
                 float* __restrict__ out) {
    float* mT    = ds_dyn;                 // [64][128]
    float* xT    = mT + 64 * 128;          // [64][128]
    float* s_xn2 = xT + 64 * 128;          // [128]
    float* amaxv = s_xn2 + 128;            // [128][8]
    int*   amaxi = (int*)(amaxv + 128*8);  // [128][8]
    float* red   = (float*)(amaxi + 128*8); // [256]

    int h = blockIdx.y, b = blockIdx.z;
    int bh = b * H + h;
    int tile = blockIdx.x;
    int s = tile >> 6;
    int t0 = (tile & 63) * 128;
    int tid = threadIdx.x;

    // fold output zeroing into s=0 blocks (replaces the 67MB serial memset)
    if (s == 0) {
        float4* o4 = (float4*)out + ((((size_t)bh * T + t0) * D) >> 2);
        float4 z = make_float4(0.f, 0.f, 0.f, 0.f);
        #pragma unroll
        for (int i = 0; i < 8; i++) o4[tid + 256 * i] = z;
    }

    const float4* mh4 = (const float4*)(means + (size_t)h * NC * D);
    for (int i = tid; i < NC * 16; i += 256) {
        int c = i & 127, dq = i >> 7;
        float4 mv = mh4[c * 16 + dq];
        mT[(4*dq+0)*128 + c] = mv.x;
        mT[(4*dq+1)*128 + c] = mv.y;
        mT[(4*dq+2)*128 + c] = mv.z;
        mT[(4*dq+3)*128 + c] = mv.w;
    }

    if (tid < 128) {
        const float* src = s ? k : q;
        const float4* xr = (const float4*)(src + ((size_t)bh * T + t0 + tid) * D);
        float4 xv[16]; float n2 = 0.f;
        #pragma unroll
        for (int i = 0; i < 16; i++) {
            float4 v = xr[i]; xv[i] = v;
            n2 += v.x*v.x + v.y*v.y + v.z*v.z + v.w*v.w;
        }
        float nrm = sqrtf(n2);
        float inv = 1.0f / fmaxf(nrm, 1e-12f);
        s_xn2[tid] = n2 * inv * inv;
        #pragma unroll
        for (int i = 0; i < 16; i++) {
            xT[(4*i+0)*128 + tid] = xv[i].x * inv;
            xT[(4*i+1)*128 + tid] = xv[i].y * inv;
            xT[(4*i+2)*128 + tid] = xv[i].z * inv;
            xT[(4*i+3)*128 + tid] = xv[i].w * inv;
        }
    }
    __syncthreads();

    int tx = tid & 31, ty = tid >> 5;      // ty == warp id: whole warp shares ty
    int cb = ty * 16;                      // 16 clusters (8 pairs) per thread
    ull acc[4][8];                         // [token j][cluster pair p]
    #pragma unroll
    for (int j = 0; j < 4; j++)
        #pragma unroll
        for (int p = 0; p < 8; p++) acc[j][p] = 0ull;

    #pragma unroll 4
    for (int d = 0; d < 64; d++) {
        const float* mrow = mT + d * 128 + cb;
        ull m0 = *(const ull*)(mrow + 0);
        ull m1 = *(const ull*)(mrow + 2);
        ull m2 = *(const ull*)(mrow + 4);
        ull m3 = *(const ull*)(mrow + 6);
        ull m4 = *(const ull*)(mrow + 8);
        ull m5 = *(const ull*)(mrow + 10);
        ull m6 = *(const ull*)(mrow + 12);
        ull m7 = *(const ull*)(mrow + 14);
        const float* xrow = xT + d * 128 + tx;
        #pragma unroll
        for (int j = 0; j < 4; j++) {
            float xv = xrow[32 * j];
            ull xx = pk2(xv, xv);
            FMA2(acc[j][0], xx, m0);
            FMA2(acc[j][1], xx, m1);
            FMA2(acc[j][2], xx, m2);
            FMA2(acc[j][3], xx, m3);
            FMA2(acc[j][4], xx, m4);
            FMA2(acc[j][5], xx, m5);
            FMA2(acc[j][6], xx, m6);
            FMA2(acc[j][7], xx, m7);
        }
    }

    size_t obase = (((size_t)bh * 2 + s) * NC) * T + t0;
    #pragma unroll
    for (int j = 0; j < 4; j++) {
        int tok = tx + 32 * j;
        float bv = -1e30f; int bc = 0;
        #pragma unroll
        for (int p = 0; p < 8; p++) {
            float2 vv = upk2(acc[j][p]);
            int c = cb + 2 * p;
            g_dists[obase + (size_t)c * T + tok]       = vv.x;
            g_dists[obase + (size_t)(c + 1) * T + tok] = vv.y;
            if (vv.x > bv) { bv = vv.x; bc = c; }
            if (vv.y > bv) { bv = vv.y; bc = c + 1; }
        }
        amaxv[tok * 8 + ty] = bv;
        amaxi[tok * 8 + ty] = bc;
    }
    __syncthreads();

    if (tid < 128) {
        float bv = -1e30f; int bc = 0;
        #pragma unroll
        for (int t2 = 0; t2 < 8; t2++) {
            float v = amaxv[tid * 8 + t2];
            if (v > bv) { bv = v; bc = amaxi[tid * 8 + t2]; }
        }
        red[tid] = s_xn2[tid] - 2.f * bv + g_mnorm2[h * NC + bc];
    } else red[tid] = 0.f;
    __syncthreads();
    for (int o = 128; o > 0; o >>= 1) {
        if (tid < o) red[tid] += red[tid + o];
        __syncthreads();
    }
    if (tid == 0) atomicAdd(&g_aux, (double)red[0]);
}

// ===================== topk: ROUND-14 exact (frozen) =====================
__global__ __launch_bounds__(512, 4) void topk_kernel() {
    __shared__ int   hist[NBINS];
    __shared__ int   warpTot[16];
    __shared__ int   warpSuf[16];
    __shared__ int   s_bstar, s_nOut, s_nCand;
    __shared__ float candV[CANDCAP];
    __shared__ int   candI[CANDCAP];

    int bid = blockIdx.x;
    int c = bid % NC;
    int s = (bid / NC) & 1;
    int bh = bid / (2 * NC);
    int h = bh % H;
    int tid = threadIdx.x;
    int lane = tid & 31, wid = tid >> 5;

    const float* dpBase = g_dists + (((size_t)bh * 2 + s) * NC + c) * T;
    const float4* dp4 = (const float4*)dpBase;

    {
        int4 z = make_int4(0, 0, 0, 0);
        ((int4*)hist)[tid]       = z;
        ((int4*)hist)[tid + 512] = z;
    }
    if (tid == 0) { s_nOut = 0; s_nCand = 0; }

    float mn = sqrtf(g_mnorm2[h * NC + c]);
    float lo = -mn;
    float scaleb = (float)NBINS / (2.0f * mn);

    unsigned bpack[8];
    {
        float4 va = dp4[tid], vb = dp4[tid + 512];
        bpack[0] = (unsigned)min(max((int)((va.x - lo) * scaleb), 0), NBINS - 1)
                 | ((unsigned)min(max((int)((va.y - lo) * scaleb), 0), NBINS - 1) << 16);
        bpack[1] = (unsigned)min(max((int)((va.z - lo) * scaleb), 0), NBINS - 1)
                 | ((unsigned)min(max((int)((va.w - lo) * scaleb), 0), NBINS - 1) << 16);
        bpack[2] = (unsigned)min(max((int)((vb.x - lo) * scaleb), 0), NBINS - 1)
                 | ((unsigned)min(max((int)((vb.y - lo) * scaleb), 0), NBINS - 1) << 16);
        bpack[3] = (unsigned)min(max((int)((vb.z - lo) * scaleb), 0), NBINS - 1)
                 | ((unsigned)min(max((int)((vb.w - lo) * scaleb), 0), NBINS - 1) << 16);
    }
    {
        float4 vc = dp4[tid + 1024], vd = dp4[tid + 1536];
        bpack[4] = (unsigned)min(max((int)((vc.x - lo) * scaleb), 0), NBINS - 1)
                 | ((unsigned)min(max((int)((vc.y - lo) * scaleb), 0), NBINS - 1) << 16);
        bpack[5] = (unsigned)min(max((int)((vc.z - lo) * scaleb), 0), NBINS - 1)
                 | ((unsigned)min(max((int)((vc.w - lo) * scaleb), 0), NBINS - 1) << 16);
        bpack[6] = (unsigned)min(max((int)((vd.x - lo) * scaleb), 0), NBINS - 1)
                 | ((unsigned)min(max((int)((vd.y - lo) * scaleb), 0), NBINS - 1) << 16);
        bpack[7] = (unsigned)min(max((int)((vd.z - lo) * scaleb), 0), NBINS - 1)
                 | ((unsigned)min(max((int)((vd.w - lo) * scaleb), 0), NBINS - 1) << 16);
    }
    __syncthreads();

    #pragma unroll
    for (int j = 0; j < 8; j++) {
        atomicAdd(&hist[bpack[j] & 0xffff], 1);
        atomicAdd(&hist[bpack[j] >> 16], 1);
    }
    __syncthreads();

    int orig = 0;
    #pragma unroll
    for (int bb = 0; bb < 8; bb++) orig += hist[tid * 8 + bb];
    int suf = orig;
    #pragma unroll
    for (int st = 1; st < 32; st <<= 1) {
        int o = __shfl_down_sync(0xffffffffu, suf, st);
        if (lane + st < 32) suf += o;
    }
    if (lane == 0) warpTot[wid] = suf;
    __syncthreads();
    if (wid == 0) {
        int t = (lane < 16) ? warpTot[lane] : 0;
        int v = t;
        #pragma unroll
        for (int st = 1; st < 16; st <<= 1) {
            int o = __shfl_down_sync(0xffffffffu, v, st);
            if (lane + st < 16) v += o;
        }
        if (lane < 16) warpSuf[lane] = v - t;
    }
    __syncthreads();

    int E = warpSuf[wid] + (suf - orig);
    if (E < W && E + orig >= W) {
        int cum = E;
        for (int bb = 7; bb >= 0; bb--) {
            int hc = hist[tid * 8 + bb];
            if (cum + hc >= W) { s_bstar = tid * 8 + bb; break; }
            cum += hc;
        }
    }
    __syncthreads();
    int bstar = s_bstar;

    int* outPtr = (s == 0 ? g_qidx : g_kidx) + ((size_t)bh * NC + c) * W;
    #pragma unroll
    for (int i = 0; i < 16; i++) {
        int bin = (int)((bpack[i >> 1] >> ((i & 1) * 16)) & 0xffffu);
        if (bin >= bstar) {
            int gi = 4 * (tid + 512 * (i >> 2)) + (i & 3);
            if (bin > bstar) {
                int p = atomicAdd(&s_nOut, 1);
                outPtr[p] = gi;
            } else {
                int p = atomicAdd(&s_nCand, 1);
                if (p < CANDCAP) { candI[p] = gi; candV[p] = dpBase[gi]; }
            }
        }
    }
    __syncthreads();

    if (tid == 0) {
        int nOut = s_nOut;
        int need = W - nOut;
        int ncand = min(s_nCand, CANDCAP);
        for (int r = 0; r < need; r++) {
            float bv = -1e30f; int bi = 0x7fffffff; int bp = -1;
            for (int m = 0; m < ncand; m++) {
                if (candI[m] >= 0) {
                    float vv = candV[m];
                    if (vv > bv || (vv == bv && candI[m] < bi)) { bv = vv; bi = candI[m]; bp = m; }
                }
            }
            outPtr[nOut + r] = bi;
            candI[bp] = -1;
        }
    }
}

// ===================== attn: ROUND-12/14 exact (FROZEN — measured optimum) =====================
#define QT_S 68
#define SC_S 72
extern __shared__ float at_dyn[];
__global__ __launch_bounds__(256, 4)
void attn_kernel(const float* __restrict__ q,
                 const float* __restrict__ k,
                 const float* __restrict__ v,
                 const float* __restrict__ mem_key,
                 const float* __restrict__ mem_value,
                 float* __restrict__ out) {
    float* qT  = at_dyn;                 // [64 d][68] swizzled, cols = q rows (pre-scaled)
    float* kT  = at_dyn + 64 * QT_S;     // [64 d][68] swizzled, cols = k rows
    float* scS = at_dyn;                 // [65 j][72]  OVERLAY (qT/kT dead)
    float* vs  = at_dyn + 2 * 64 * QT_S; // [65 j][64 d]
    float* kMem = vs + 65 * 64;          // [64]
    int* qi = (int*)(kMem + 64);
    int* ki = qi + 64;

    int bid = blockIdx.x;
    int c = bid % NC;
    int bh = bid / NC;
    int h = bh % H;
    int tid = threadIdx.x;

    if (tid < 64)       qi[tid]      = g_qidx[((size_t)bh * NC + c) * W + tid];
    else if (tid < 128) ki[tid - 64] = g_kidx[((size_t)bh * NC + c) * W + tid - 64];
    __syncthreads();

    const float scale = 0.125f;   // d^-0.5 folded into q
    #pragma unroll
    for (int it = 0; it < 4; it++) {
        int idx = tid + 256 * it;           // 1024 slots = 64 rows x 16 float4
        int r = idx >> 4, c4 = idx & 15;
        int sw = 4 * (c4 & 7);
        float4 qv = ((const float4*)(q + ((size_t)bh * T + qi[r]) * D))[c4];
        qT[(4*c4+0)*QT_S + (r ^ sw)] = qv.x * scale;
        qT[(4*c4+1)*QT_S + (r ^ sw)] = qv.y * scale;
        qT[(4*c4+2)*QT_S + (r ^ sw)] = qv.z * scale;
        qT[(4*c4+3)*QT_S + (r ^ sw)] = qv.w * scale;
        float4 kv = ((const float4*)(k + ((size_t)bh * T + ki[r]) * D))[c4];
        kT[(4*c4+0)*QT_S + (r ^ sw)] = kv.x;
        kT[(4*c4+1)*QT_S + (r ^ sw)] = kv.y;
        kT[(4*c4+2)*QT_S + (r ^ sw)] = kv.z;
        kT[(4*c4+3)*QT_S + (r ^ sw)] = kv.w;
        ((float4*)(vs + r * 64))[c4] = ((const float4*)(v + ((size_t)bh * T + ki[r]) * D))[c4];
    }
    if (tid < 16) {
        ((float4*)kMem)[tid] = ((const float4*)(mem_key + ((size_t)h * NC + c) * D))[tid];
        ((float4*)(vs + 64 * 64))[tid] = ((const float4*)(mem_value + ((size_t)h * NC + c) * D))[tid];
    }
    __syncthreads();

    int tx = tid & 15, ty = tid >> 4;
    int qb = 4 * tx, kb = 4 * ty;

    ull acc[2][4];
    #pragma unroll
    for (int p = 0; p < 2; p++)
        #pragma unroll
        for (int i = 0; i < 4; i++) acc[p][i] = 0ull;
    #pragma unroll
    for (int d = 0; d < 64; d++) {
        const int cw = 4 * ((d >> 2) & 7);
        ulonglong2 q2 = *(const ulonglong2*)(qT + d * QT_S + (qb ^ cw));
        float4 k4 = *(const float4*)(kT + d * QT_S + (kb ^ cw));
        ull k0 = pk2(k4.x, k4.x), k1 = pk2(k4.y, k4.y);
        ull k2 = pk2(k4.z, k4.z), k3 = pk2(k4.w, k4.w);
        FMA2(acc[0][0], q2.x, k0); FMA2(acc[1][0], q2.y, k0);
        FMA2(acc[0][1], q2.x, k1); FMA2(acc[1][1], q2.y, k1);
        FMA2(acc[0][2], q2.x, k2); FMA2(acc[1][2], q2.y, k2);
        FMA2(acc[0][3], q2.x, k3); FMA2(acc[1][3], q2.y, k3);
    }
    float memcol = 0.f;
    if (tid < 64) {
        #pragma unroll
        for (int d = 0; d < 64; d++)
            memcol += qT[d * QT_S + (tid ^ (4 * ((d >> 2) & 7)))] * kMem[d];
    }
    __syncthreads();   // qT/kT consumed; scS overlays

    #pragma unroll
    for (int i = 0; i < 4; i++) {
        ulonglong2 st; st.x = acc[0][i]; st.y = acc[1][i];
        *(ulonglong2*)(scS + (kb + i) * SC_S + qb) = st;
    }
    if (tid < 64) scS[64 * SC_S + tid] = memcol;
    __syncthreads();

    {
        int row = tid >> 2, part = tid & 3;
        float mx = -1e30f;
        for (int j = part; j < 65; j += 4) mx = fmaxf(mx, scS[j * SC_S + row]);
        mx = fmaxf(mx, __shfl_xor_sync(0xffffffffu, mx, 1));
        mx = fmaxf(mx, __shfl_xor_sync(0xffffffffu, mx, 2));
        float sum = 0.f;
        for (int j = part; j < 65; j += 4) {
            float e = __expf(scS[j * SC_S + row] - mx);
            scS[j * SC_S + row] = e;
            sum += e;
        }
        sum += __shfl_xor_sync(0xffffffffu, sum, 1);
        sum += __shfl_xor_sync(0xffffffffu, sum, 2);
        float rinv = 1.0f / sum;
        for (int j = part; j < 65; j += 4) scS[j * SC_S + row] *= rinv;
    }
    __syncthreads();

    {
        int db = 4 * ty;
        ull o2[2][4];
        #pragma unroll
        for (int p = 0; p < 2; p++)
            #pragma unroll
            for (int i = 0; i < 4; i++) o2[p][i] = 0ull;
        #pragma unroll
        for (int j = 0; j < 65; j++) {
            ulonglong2 p2 = *(const ulonglong2*)(scS + j * SC_S + qb);
            float4 v4 = *(const float4*)(vs + j * 64 + db);
            ull v0 = pk2(v4.x, v4.x), v1 = pk2(v4.y, v4.y);
            ull v2 = pk2(v4.z, v4.z), v3 = pk2(v4.w, v4.w);
            FMA2(o2[0][0], p2.x, v0); FMA2(o2[1][0], p2.y, v0);
            FMA2(o2[0][1], p2.x, v1); FMA2(o2[1][1], p2.y, v1);
            FMA2(o2[0][2], p2.x, v2); FMA2(o2[1][2], p2.y, v2);
            FMA2(o2[0][3], p2.x, v3); FMA2(o2[1][3], p2.y, v3);
        }
        #pragma unroll
        for (int p = 0; p < 2; p++) {
            int r0 = qb + 2 * p;
            float* opA = out + ((size_t)bh * T + qi[r0])     * D + db;
            float* opB = out + ((size_t)bh * T + qi[r0 + 1]) * D + db;
            float2 f0 = upk2(o2[p][0]), f1 = upk2(o2[p][1]);
            float2 f2 = upk2(o2[p][2]), f3 = upk2(o2[p][3]);
            RED4(opA, f0.x, f1.x, f2.x, f3.x);
            RED4(opB, f0.y, f1.y, f2.y, f3.y);
        }
    }
    if (tid < 64) atomicAdd(&g_cnt[(size_t)bh * T + qi[tid]], 1.0f);
}

__global__ void finalize_kernel(float* out, int out_size) {
    int i = blockIdx.x * blockDim.x + threadIdx.x;
    float4* o4 = (float4*)out;
    #pragma unroll
    for (int u = 0; u < 2; u++) {
        int idx = i + u * (NOUT / 8);
        float s = 1.0f / (g_cnt[idx >> 4] + 1e-5f);
        float4 vv = o4[idx];
        vv.x *= s; vv.y *= s; vv.z *= s; vv.w *= s;
        o4[idx] = vv;
    }
    if (i == 0 && out_size > NOUT) {
        out[NOUT] = (float)(g_aux / ((double)B * H * 2 * T * D) * 1e-4);
    }
}

extern "C" void kernel_launch(void* const* d_in, const int* in_sizes, int n_in,
                              void* d_out, int out_size) {
    const float* q         = (const float*)d_in[0];
    const float* k         = (const float*)d_in[1];
    const float* v         = (const float*)d_in[2];
    const float* means     = (const float*)d_in[3];
    const float* mem_key   = (const float*)d_in[4];
    const float* mem_value = (const float*)d_in[5];
    float* out = (float*)d_out;

    int ds_smem = (64*128 + 64*128 + 128 + 128*8 + 128*8 + 256) * 4;  // 75264
    int at_smem = (2*64*QT_S + 65*64 + 64 + 128) * 4;                 // 52224
    cudaFuncSetAttribute(dist_kernel, cudaFuncAttributeMaxDynamicSharedMemorySize, ds_smem);
    cudaFuncSetAttribute(attn_kernel, cudaFuncAttributeMaxDynamicSharedMemorySize, at_smem);

    void* pcnt = nullptr; void* paux = nullptr;
    cudaGetSymbolAddress(&pcnt, g_cnt);
    cudaGetSymbolAddress(&paux, g_aux);

    // out[0..NOUT) is zeroed inside dist_kernel (s==0 blocks); only the tail needs a memset
    if (out_size > NOUT)
        cudaMemsetAsync(out + NOUT, 0, (size_t)(out_size - NOUT) * sizeof(float), 0);
    cudaMemsetAsync(pcnt, 0, (size_t)NTOK * sizeof(float), 0);
    cudaMemsetAsync(paux, 0, sizeof(double), 0);
    mnorm_kernel<<<(H * NC + 255) / 256, 256>>>(means);
    dist_kernel<<<dim3(128, H, B), 256, ds_smem>>>(q, k, means, out);
    topk_kernel<<<B * H * 2 * NC, 512>>>();
    attn_kernel<<<B * H * NC, 256, at_smem>>>(q, k, v, mem_key, mem_value, out);
    finalize_kernel<<<(NOUT / 8 + 255) / 256, 256>>>(out, out_size);
}

// round 16
// speedup vs baseline: 1.2693x; 1.0305x over previous
#include <cuda_runtime.h>
#include <math.h>

#define B 4
#define H 8
#define T 8192
#define D 64
#define NC 128
#define W 64
#define NTOK (B*H*T)          /* 262144 */
#define NOUT (B*H*T*D)        /* 16777216 */
#define NBINS 4096
#define CANDCAP 512

typedef unsigned long long ull;

// packed fp32x2 FMA (Blackwell double-rate fp32; only reachable via PTX)
#define FMA2(acc, a, b) asm("fma.rn.f32x2 %0, %1, %2, %0;" : "+l"(acc) : "l"(a), "l"(b))
// vectorized float reduction to global (sm_90+)
#define RED4(p, a, b, c, d) asm volatile("red.global.add.v4.f32 [%0], {%1,%2,%3,%4};" :: "l"(p), "f"(a), "f"(b), "f"(c), "f"(d) : "memory")

__device__ __forceinline__ ull pk2(float a, float b) {
    ull r;
    asm("mov.b64 %0, {%1, %2};" : "=l"(r) : "r"(__float_as_uint(a)), "r"(__float_as_uint(b)));
    return r;
}
__device__ __forceinline__ float2 upk2(ull p) {
    unsigned lo, hi;
    asm("mov.b64 {%0, %1}, %2;" : "=r"(lo), "=r"(hi) : "l"(p));
    return make_float2(__uint_as_float(lo), __uint_as_float(hi));
}

// -------- device scratch (no allocations allowed) --------
__device__ float  g_dists[(size_t)B*H*2*NC*T];   // [bh][s][c][t]
__device__ float  g_mnorm2[H*NC];
__device__ int    g_qidx[B*H*NC*W];
__device__ int    g_kidx[B*H*NC*W];
__device__ float  g_cnt[NTOK];
__device__ double g_aux;

// ---------------------------------------------------------
__global__ void mnorm_kernel(const float* __restrict__ means) {
    int i = blockIdx.x * blockDim.x + threadIdx.x;
    if (i < H * NC) {
        const float* m = means + (size_t)i * D;
        float s = 0.f;
        #pragma unroll
        for (int d = 0; d < D; d++) { float x = m[d]; s += x * x; }
        g_mnorm2[i] = s;
    }
}

// count q-index occurrences (B*H*NC*W entries); runs after topk, before attn
__global__ void count_kernel() {
    int i = blockIdx.x * blockDim.x + threadIdx.x;   // [0, B*H*NC*W)
    int bh = i >> 13;                                // / (NC*W)
    atomicAdd(&g_cnt[(size_t)bh * T + g_qidx[i]], 1.0f);
}

// ===================== dist: 4tok x 16cl tile (warp-uniform ty -> all m-loads broadcast) =====================
extern __shared__ float ds_dyn[];
__global__ __launch_bounds__(256, 2)
void dist_kernel(const float* __restrict__ q,
                 const float* __restrict__ k,
                 const float* __restrict__ means,
                 float* __restrict__ out) {
    float* mT    = ds_dyn;                 // [64][128]
    float* xT    = mT + 64 * 128;          // [64][128]
    float* s_xn2 = xT + 64 * 128;          // [128]
    float* amaxv = s_xn2 + 128;            // [128][8]
    int*   amaxi = (int*)(amaxv + 128*8);  // [128][8]
    float* red   = (float*)(amaxi + 128*8); // [256]

    int h = blockIdx.y, b = blockIdx.z;
    int bh = b * H + h;
    int tile = blockIdx.x;
    int s = tile >> 6;
    int t0 = (tile & 63) * 128;
    int tid = threadIdx.x;

    // fold output zeroing into s=0 blocks (replaces the 67MB serial memset)
    if (s == 0) {
        float4* o4 = (float4*)out + ((((size_t)bh * T + t0) * D) >> 2);
        float4 z = make_float4(0.f, 0.f, 0.f, 0.f);
        #pragma unroll
        for (int i = 0; i < 8; i++) o4[tid + 256 * i] = z;
    }

    const float4* mh4 = (const float4*)(means + (size_t)h * NC * D);
    for (int i = tid; i < NC * 16; i += 256) {
        int c = i & 127, dq = i >> 7;
        float4 mv = mh4[c * 16 + dq];
        mT[(4*dq+0)*128 + c] = mv.x;
        mT[(4*dq+1)*128 + c] = mv.y;
        mT[(4*dq+2)*128 + c] = mv.z;
        mT[(4*dq+3)*128 + c] = mv.w;
    }

    if (tid < 128) {
        const float* src = s ? k : q;
        const float4* xr = (const float4*)(src + ((size_t)bh * T + t0 + tid) * D);
        float4 xv[16]; float n2 = 0.f;
        #pragma unroll
        for (int i = 0; i < 16; i++) {
            float4 v = xr[i]; xv[i] = v;
            n2 += v.x*v.x + v.y*v.y + v.z*v.z + v.w*v.w;
        }
        float nrm = sqrtf(n2);
        float inv = 1.0f / fmaxf(nrm, 1e-12f);
        s_xn2[tid] = n2 * inv * inv;
        #pragma unroll
        for (int i = 0; i < 16; i++) {
            xT[(4*i+0)*128 + tid] = xv[i].x * inv;
            xT[(4*i+1)*128 + tid] = xv[i].y * inv;
            xT[(4*i+2)*128 + tid] = xv[i].z * inv;
            xT[(4*i+3)*128 + tid] = xv[i].w * inv;
        }
    }
    __syncthreads();

    int tx = tid & 31, ty = tid >> 5;      // ty == warp id: whole warp shares ty
    int cb = ty * 16;                      // 16 clusters (8 pairs) per thread
    ull acc[4][8];                         // [token j][cluster pair p]
    #pragma unroll
    for (int j = 0; j < 4; j++)
        #pragma unroll
        for (int p = 0; p < 8; p++) acc[j][p] = 0ull;

    #pragma unroll 4
    for (int d = 0; d < 64; d++) {
        const float* mrow = mT + d * 128 + cb;
        ull m0 = *(const ull*)(mrow + 0);
        ull m1 = *(const ull*)(mrow + 2);
        ull m2 = *(const ull*)(mrow + 4);
        ull m3 = *(const ull*)(mrow + 6);
        ull m4 = *(const ull*)(mrow + 8);
        ull m5 = *(const ull*)(mrow + 10);
        ull m6 = *(const ull*)(mrow + 12);
        ull m7 = *(const ull*)(mrow + 14);
        const float* xrow = xT + d * 128 + tx;
        #pragma unroll
        for (int j = 0; j < 4; j++) {
            float xv = xrow[32 * j];
            ull xx = pk2(xv, xv);
            FMA2(acc[j][0], xx, m0);
            FMA2(acc[j][1], xx, m1);
            FMA2(acc[j][2], xx, m2);
            FMA2(acc[j][3], xx, m3);
            FMA2(acc[j][4], xx, m4);
            FMA2(acc[j][5], xx, m5);
            FMA2(acc[j][6], xx, m6);
            FMA2(acc[j][7], xx, m7);
        }
    }

    size_t obase = (((size_t)bh * 2 + s) * NC) * T + t0;
    #pragma unroll
    for (int j = 0; j < 4; j++) {
        int tok = tx + 32 * j;
        float bv = -1e30f; int bc = 0;
        #pragma unroll
        for (int p = 0; p < 8; p++) {
            float2 vv = upk2(acc[j][p]);
            int c = cb + 2 * p;
            g_dists[obase + (size_t)c * T + tok]       = vv.x;
            g_dists[obase + (size_t)(c + 1) * T + tok] = vv.y;
            if (vv.x > bv) { bv = vv.x; bc = c; }
            if (vv.y > bv) { bv = vv.y; bc = c + 1; }
        }
        amaxv[tok * 8 + ty] = bv;
        amaxi[tok * 8 + ty] = bc;
    }
    __syncthreads();

    if (tid < 128) {
        float bv = -1e30f; int bc = 0;
        #pragma unroll
        for (int t2 = 0; t2 < 8; t2++) {
            float v = amaxv[tid * 8 + t2];
            if (v > bv) { bv = v; bc = amaxi[tid * 8 + t2]; }
        }
        red[tid] = s_xn2[tid] - 2.f * bv + g_mnorm2[h * NC + bc];
    } else red[tid] = 0.f;
    __syncthreads();
    for (int o = 128; o > 0; o >>= 1) {
        if (tid < o) red[tid] += red[tid + o];
        __syncthreads();
    }
    if (tid == 0) atomicAdd(&g_aux, (double)red[0]);
}

// ===================== topk: ROUND-14 exact (frozen) =====================
__global__ __launch_bounds__(512, 4) void topk_kernel() {
    __shared__ int   hist[NBINS];
    __shared__ int   warpTot[16];
    __shared__ int   warpSuf[16];
    __shared__ int   s_bstar, s_nOut, s_nCand;
    __shared__ float candV[CANDCAP];
    __shared__ int   candI[CANDCAP];

    int bid = blockIdx.x;
    int c = bid % NC;
    int s = (bid / NC) & 1;
    int bh = bid / (2 * NC);
    int h = bh % H;
    int tid = threadIdx.x;
    int lane = tid & 31, wid = tid >> 5;

    const float* dpBase = g_dists + (((size_t)bh * 2 + s) * NC + c) * T;
    const float4* dp4 = (const float4*)dpBase;

    {
        int4 z = make_int4(0, 0, 0, 0);
        ((int4*)hist)[tid]       = z;
        ((int4*)hist)[tid + 512] = z;
    }
    if (tid == 0) { s_nOut = 0; s_nCand = 0; }

    float mn = sqrtf(g_mnorm2[h * NC + c]);
    float lo = -mn;
    float scaleb = (float)NBINS / (2.0f * mn);

    unsigned bpack[8];
    {
        float4 va = dp4[tid], vb = dp4[tid + 512];
        bpack[0] = (unsigned)min(max((int)((va.x - lo) * scaleb), 0), NBINS - 1)
                 | ((unsigned)min(max((int)((va.y - lo) * scaleb), 0), NBINS - 1) << 16);
        bpack[1] = (unsigned)min(max((int)((va.z - lo) * scaleb), 0), NBINS - 1)
                 | ((unsigned)min(max((int)((va.w - lo) * scaleb), 0), NBINS - 1) << 16);
        bpack[2] = (unsigned)min(max((int)((vb.x - lo) * scaleb), 0), NBINS - 1)
                 | ((unsigned)min(max((int)((vb.y - lo) * scaleb), 0), NBINS - 1) << 16);
        bpack[3] = (unsigned)min(max((int)((vb.z - lo) * scaleb), 0), NBINS - 1)
                 | ((unsigned)min(max((int)((vb.w - lo) * scaleb), 0), NBINS - 1) << 16);
    }
    {
        float4 vc = dp4[tid + 1024], vd = dp4[tid + 1536];
        bpack[4] = (unsigned)min(max((int)((vc.x - lo) * scaleb), 0), NBINS - 1)
                 | ((unsigned)min(max((int)((vc.y - lo) * scaleb), 0), NBINS - 1) << 16);
        bpack[5] = (unsigned)min(max((int)((vc.z - lo) * scaleb), 0), NBINS - 1)
                 | ((unsigned)min(max((int)((vc.w - lo) * scaleb), 0), NBINS - 1) << 16);
        bpack[6] = (unsigned)min(max((int)((vd.x - lo) * scaleb), 0), NBINS - 1)
                 | ((unsigned)min(max((int)((vd.y - lo) * scaleb), 0), NBINS - 1) << 16);
        bpack[7] = (unsigned)min(max((int)((vd.z - lo) * scaleb), 0), NBINS - 1)
                 | ((unsigned)min(max((int)((vd.w - lo) * scaleb), 0), NBINS - 1) << 16);
    }
    __syncthreads();

    #pragma unroll
    for (int j = 0; j < 8; j++) {
        atomicAdd(&hist[bpack[j] & 0xffff], 1);
        atomicAdd(&hist[bpack[j] >> 16], 1);
    }
    __syncthreads();

    int orig = 0;
    #pragma unroll
    for (int bb = 0; bb < 8; bb++) orig += hist[tid * 8 + bb];
    int suf = orig;
    #pragma unroll
    for (int st = 1; st < 32; st <<= 1) {
        int o = __shfl_down_sync(0xffffffffu, suf, st);
        if (lane + st < 32) suf += o;
    }
    if (lane == 0) warpTot[wid] = suf;
    __syncthreads();
    if (wid == 0) {
        int t = (lane < 16) ? warpTot[lane] : 0;
        int v = t;
        #pragma unroll
        for (int st = 1; st < 16; st <<= 1) {
            int o = __shfl_down_sync(0xffffffffu, v, st);
            if (lane + st < 16) v += o;
        }
        if (lane < 16) warpSuf[lane] = v - t;
    }
    __syncthreads();

    int E = warpSuf[wid] + (suf - orig);
    if (E < W && E + orig >= W) {
        int cum = E;
        for (int bb = 7; bb >= 0; bb--) {
            int hc = hist[tid * 8 + bb];
            if (cum + hc >= W) { s_bstar = tid * 8 + bb; break; }
            cum += hc;
        }
    }
    __syncthreads();
    int bstar = s_bstar;

    int* outPtr = (s == 0 ? g_qidx : g_kidx) + ((size_t)bh * NC + c) * W;
    #pragma unroll
    for (int i = 0; i < 16; i++) {
        int bin = (int)((bpack[i >> 1] >> ((i & 1) * 16)) & 0xffffu);
        if (bin >= bstar) {
            int gi = 4 * (tid + 512 * (i >> 2)) + (i & 3);
            if (bin > bstar) {
                int p = atomicAdd(&s_nOut, 1);
                outPtr[p] = gi;
            } else {
                int p = atomicAdd(&s_nCand, 1);
                if (p < CANDCAP) { candI[p] = gi; candV[p] = dpBase[gi]; }
            }
        }
    }
    __syncthreads();

    if (tid == 0) {
        int nOut = s_nOut;
        int need = W - nOut;
        int ncand = min(s_nCand, CANDCAP);
        for (int r = 0; r < need; r++) {
            float bv = -1e30f; int bi = 0x7fffffff; int bp = -1;
            for (int m = 0; m < ncand; m++) {
                if (candI[m] >= 0) {
                    float vv = candV[m];
                    if (vv > bv || (vv == bv && candI[m] < bi)) { bv = vv; bi = candI[m]; bp = m; }
                }
            }
            outPtr[nOut + r] = bi;
            candI[bp] = -1;
        }
    }
}

// ===================== attn: r12/14 core + pre-scaled scatter (finalize folded in) =====================
#define QT_S 68
#define SC_S 72
extern __shared__ float at_dyn[];
__global__ __launch_bounds__(256, 4)
void attn_kernel(const float* __restrict__ q,
                 const float* __restrict__ k,
                 const float* __restrict__ v,
                 const float* __restrict__ mem_key,
                 const float* __restrict__ mem_value,
                 float* __restrict__ out, int out_size) {
    float* qT  = at_dyn;                 // [64 d][68] swizzled, cols = q rows (pre-scaled)
    float* kT  = at_dyn + 64 * QT_S;     // [64 d][68] swizzled, cols = k rows
    float* scS = at_dyn;                 // [65 j][72]  OVERLAY (qT/kT dead)
    float* vs  = at_dyn + 2 * 64 * QT_S; // [65 j][64 d]
    float* kMem = vs + 65 * 64;          // [64]
    float* cntS = kMem + 64;             // [64] 1/(count+eps) per q row
    int* qi = (int*)(cntS + 64);
    int* ki = qi + 64;

    int bid = blockIdx.x;
    int c = bid % NC;
    int bh = bid / NC;
    int h = bh % H;
    int tid = threadIdx.x;

    // block 0 writes the aux-loss tail (g_aux complete: dist finished before attn)
    if (bid == 0 && tid == 0 && out_size > NOUT) {
        out[NOUT] = (float)(g_aux / ((double)B * H * 2 * T * D) * 1e-4);
    }

    if (tid < 64)       qi[tid]      = g_qidx[((size_t)bh * NC + c) * W + tid];
    else if (tid < 128) ki[tid - 64] = g_kidx[((size_t)bh * NC + c) * W + tid - 64];
    __syncthreads();

    const float scale = 0.125f;   // d^-0.5 folded into q
    #pragma unroll
    for (int it = 0; it < 4; it++) {
        int idx = tid + 256 * it;           // 1024 slots = 64 rows x 16 float4
        int r = idx >> 4, c4 = idx & 15;
        int sw = 4 * (c4 & 7);
        float4 qv = ((const float4*)(q + ((size_t)bh * T + qi[r]) * D))[c4];
        qT[(4*c4+0)*QT_S + (r ^ sw)] = qv.x * scale;
        qT[(4*c4+1)*QT_S + (r ^ sw)] = qv.y * scale;
        qT[(4*c4+2)*QT_S + (r ^ sw)] = qv.z * scale;
        qT[(4*c4+3)*QT_S + (r ^ sw)] = qv.w * scale;
        float4 kv = ((const float4*)(k + ((size_t)bh * T + ki[r]) * D))[c4];
        kT[(4*c4+0)*QT_S + (r ^ sw)] = kv.x;
        kT[(4*c4+1)*QT_S + (r ^ sw)] = kv.y;
        kT[(4*c4+2)*QT_S + (r ^ sw)] = kv.z;
        kT[(4*c4+3)*QT_S + (r ^ sw)] = kv.w;
        ((float4*)(vs + r * 64))[c4] = ((const float4*)(v + ((size_t)bh * T + ki[r]) * D))[c4];
    }
    if (tid < 16) {
        ((float4*)kMem)[tid] = ((const float4*)(mem_key + ((size_t)h * NC + c) * D))[tid];
        ((float4*)(vs + 64 * 64))[tid] = ((const float4*)(mem_value + ((size_t)h * NC + c) * D))[tid];
    }
    __syncthreads();

    int tx = tid & 15, ty = tid >> 4;
    int qb = 4 * tx, kb = 4 * ty;

    ull acc[2][4];
    #pragma unroll
    for (int p = 0; p < 2; p++)
        #pragma unroll
        for (int i = 0; i < 4; i++) acc[p][i] = 0ull;
    #pragma unroll
    for (int d = 0; d < 64; d++) {
        const int cw = 4 * ((d >> 2) & 7);
        ulonglong2 q2 = *(const ulonglong2*)(qT + d * QT_S + (qb ^ cw));
        float4 k4 = *(const float4*)(kT + d * QT_S + (kb ^ cw));
        ull k0 = pk2(k4.x, k4.x), k1 = pk2(k4.y, k4.y);
        ull k2 = pk2(k4.z, k4.z), k3 = pk2(k4.w, k4.w);
        FMA2(acc[0][0], q2.x, k0); FMA2(acc[1][0], q2.y, k0);
        FMA2(acc[0][1], q2.x, k1); FMA2(acc[1][1], q2.y, k1);
        FMA2(acc[0][2], q2.x, k2); FMA2(acc[1][2], q2.y, k2);
        FMA2(acc[0][3], q2.x, k3); FMA2(acc[1][3], q2.y, k3);
    }
    float memcol = 0.f;
    if (tid < 64) {
        #pragma unroll
        for (int d = 0; d < 64; d++)
            memcol += qT[d * QT_S + (tid ^ (4 * ((d >> 2) & 7)))] * kMem[d];
    }
    __syncthreads();   // qT/kT consumed; scS overlays

    #pragma unroll
    for (int i = 0; i < 4; i++) {
        ulonglong2 st; st.x = acc[0][i]; st.y = acc[1][i];
        *(ulonglong2*)(scS + (kb + i) * SC_S + qb) = st;
    }
    if (tid < 64) {
        scS[64 * SC_S + tid] = memcol;
        cntS[tid] = 1.0f / (g_cnt[(size_t)bh * T + qi[tid]] + 1e-5f);
    }
    __syncthreads();

    {
        int row = tid >> 2, part = tid & 3;
        float mx = -1e30f;
        for (int j = part; j < 65; j += 4) mx = fmaxf(mx, scS[j * SC_S + row]);
        mx = fmaxf(mx, __shfl_xor_sync(0xffffffffu, mx, 1));
        mx = fmaxf(mx, __shfl_xor_sync(0xffffffffu, mx, 2));
        float sum = 0.f;
        for (int j = part; j < 65; j += 4) {
            float e = __expf(scS[j * SC_S + row] - mx);
            scS[j * SC_S + row] = e;
            sum += e;
        }
        sum += __shfl_xor_sync(0xffffffffu, sum, 1);
        sum += __shfl_xor_sync(0xffffffffu, sum, 2);
        float rinv = 1.0f / sum;
        for (int j = part; j < 65; j += 4) scS[j * SC_S + row] *= rinv;
    }
    __syncthreads();

    {
        int db = 4 * ty;
        ull o2[2][4];
        #pragma unroll
        for (int p = 0; p < 2; p++)
            #pragma unroll
            for (int i = 0; i < 4; i++) o2[p][i] = 0ull;
        #pragma unroll
        for (int j = 0; j < 65; j++) {
            ulonglong2 p2 = *(const ulonglong2*)(scS + j * SC_S + qb);
            float4 v4 = *(const float4*)(vs + j * 64 + db);
            ull v0 = pk2(v4.x, v4.x), v1 = pk2(v4.y, v4.y);
            ull v2 = pk2(v4.z, v4.z), v3 = pk2(v4.w, v4.w);
            FMA2(o2[0][0], p2.x, v0); FMA2(o2[1][0], p2.y, v0);
            FMA2(o2[0][1], p2.x, v1); FMA2(o2[1][1], p2.y, v1);
            FMA2(o2[0][2], p2.x, v2); FMA2(o2[1][2], p2.y, v2);
            FMA2(o2[0][3], p2.x, v3); FMA2(o2[1][3], p2.y, v3);
        }
        #pragma unroll
        for (int p = 0; p < 2; p++) {
            int r0 = qb + 2 * p;
            float sA = cntS[r0], sB = cntS[r0 + 1];
            float* opA = out + ((size_t)bh * T + qi[r0])     * D + db;
            float* opB = out + ((size_t)bh * T + qi[r0 + 1]) * D + db;
            float2 f0 = upk2(o2[p][0]), f1 = upk2(o2[p][1]);
            float2 f2 = upk2(o2[p][2]), f3 = upk2(o2[p][3]);
            RED4(opA, f0.x * sA, f1.x * sA, f2.x * sA, f3.x * sA);
            RED4(opB, f0.y * sB, f1.y * sB, f2.y * sB, f3.y * sB);
        }
    }
}

extern "C" void kernel_launch(void* const* d_in, const int* in_sizes, int n_in,
                              void* d_out, int out_size) {
    const float* q         = (const float*)d_in[0];
    const float* k         = (const float*)d_in[1];
    const float* v         = (const float*)d_in[2];
    const float* means     = (const float*)d_in[3];
    const float* mem_key   = (const float*)d_in[4];
    const float* mem_value = (const float*)d_in[5];
    float* out = (float*)d_out;

    int ds_smem = (64*128 + 64*128 + 128 + 128*8 + 128*8 + 256) * 4;  // 75264
    int at_smem = (2*64*QT_S + 65*64 + 64 + 64 + 128) * 4;            // 52480
    cudaFuncSetAttribute(dist_kernel, cudaFuncAttributeMaxDynamicSharedMemorySize, ds_smem);
    cudaFuncSetAttribute(attn_kernel, cudaFuncAttributeMaxDynamicSharedMemorySize, at_smem);

    void* pcnt = nullptr; void* paux = nullptr;
    cudaGetSymbolAddress(&pcnt, g_cnt);
    cudaGetSymbolAddress(&paux, g_aux);

    // out[0..NOUT) is zeroed inside dist_kernel (s==0 blocks); tail zeroed here,
    // then attn block 0 writes the aux value over it
    if (out_size > NOUT)
        cudaMemsetAsync(out + NOUT, 0, (size_t)(out_size - NOUT) * sizeof(float), 0);
    cudaMemsetAsync(pcnt, 0, (size_t)NTOK * sizeof(float), 0);
    cudaMemsetAsync(paux, 0, sizeof(double), 0);
    mnorm_kernel<<<(H * NC + 255) / 256, 256>>>(means);
    dist_kernel<<<dim3(128, H, B), 256, ds_smem>>>(q, k, means, out);
    topk_kernel<<<B * H * 2 * NC, 512>>>();
    count_kernel<<<B * H * NC * W / 256, 256>>>();
    attn_kernel<<<B * H * NC, 256, at_smem>>>(q, k, v, mem_key, mem_value, out, out_size);
}